// round 1
// baseline (speedup 1.0000x reference)
#include <cuda_runtime.h>
#include <cuda_bf16.h>

// ---------------------------------------------------------------------------
// HGNN: 2-layer GCN + masked-sum + MLP head, pruned to the dependency cone of
// the masked node(s). Only full-graph work: degree scatter + 2 edge scans.
// ---------------------------------------------------------------------------

#define NMAX     100000
#define MAX_S2   256
#define MAX_L2E  8192
#define MAX_S1   (MAX_L2E + MAX_S2)   // 8448

__device__ float              g_deg[NMAX];        // scatter-only; true deg = g_deg + 1 (self loop)
__device__ int                g_mapS1[NMAX];
__device__ int                g_mapS2[NMAX];
__device__ int                g_s2_node[MAX_S2];
__device__ float              g_s2_val[MAX_S2];
__device__ int                g_l2_row[MAX_L2E];
__device__ int                g_l2_cslot[MAX_L2E];
__device__ float              g_l2_w[MAX_L2E];
__device__ int                g_s1_node[MAX_S1];
__device__ float              g_agg0[MAX_S1 * 128];
__device__ float              g_h1[MAX_S1 * 256];
__device__ float              g_agg1[MAX_S2 * 256];
__device__ float              g_z[256];
__device__ int                g_s2_count;
__device__ int                g_l2e_count;
__device__ int                g_s1_count;
__device__ int                g_is32;
__device__ unsigned long long g_argmax_key;

// ---------------------------------------------------------------------------
__global__ void k_init(int n) {
    int i = blockIdx.x * blockDim.x + threadIdx.x;
    if (i < n) { g_deg[i] = 0.0f; g_mapS1[i] = -1; g_mapS2[i] = -1; }
    if (i < MAX_S1 * 128) g_agg0[i] = 0.0f;
    if (i < MAX_S2 * 256) g_agg1[i] = 0.0f;
    if (i < 256)          g_z[i] = 0.0f;
    if (i == 0) {
        g_s2_count = 0; g_l2e_count = 0; g_s1_count = 0; g_is32 = 0;
        g_argmax_key = 0ull;
    }
}

// Detect whether edge_index is really int64 or silently-downcast int32.
// Reads only the first min(E,4096) int64 slots (safe for both layouts).
__global__ void k_detect(const long long* __restrict__ ei, int E, int n) {
    int i = blockIdx.x * blockDim.x + threadIdx.x;
    int lim = E < 4096 ? E : 4096;
    if (i < lim) {
        long long v = ei[i];
        if (v < 0 || v >= (long long)n) atomicExch(&g_is32, 1);
    }
}

// Mask scan: build S2 (nonzero mask nodes) + block-reduced argmax (first max).
__global__ void k_mask(const float* __restrict__ mask, int n) {
    __shared__ unsigned long long sk[256];
    int i = blockIdx.x * blockDim.x + threadIdx.x;
    unsigned long long key = 0ull;
    if (i < n) {
        float m = mask[i];
        if (m != 0.0f) {
            int slot = atomicAdd(&g_s2_count, 1);
            if (slot < MAX_S2) {
                g_s2_node[slot] = i;
                g_s2_val[slot]  = m;
                g_mapS2[i]      = slot;
            }
        }
        unsigned int b  = __float_as_uint(m);
        unsigned int ub = (b & 0x80000000u) ? ~b : (b | 0x80000000u);  // order-preserving
        key = (((unsigned long long)ub) << 32) |
              (unsigned long long)(0xFFFFFFFFu - (unsigned)i);          // ties -> smallest i
    }
    sk[threadIdx.x] = key;
    __syncthreads();
    for (int o = 128; o > 0; o >>= 1) {
        if (threadIdx.x < o) {
            unsigned long long a = sk[threadIdx.x], b2 = sk[threadIdx.x + o];
            sk[threadIdx.x] = (a > b2) ? a : b2;
        }
        __syncthreads();
    }
    if (threadIdx.x == 0) atomicMax(&g_argmax_key, sk[0]);
}

// Edge scan 1: degree scatter + record edges into S2.
__global__ void k_scan1(const long long* __restrict__ ei64,
                        const float* __restrict__ ew, int E) {
    int e = blockIdx.x * blockDim.x + threadIdx.x;
    if (e >= E) return;
    int is32 = g_is32;
    const int* ei32 = (const int*)ei64;
    int c = is32 ? ei32[E + e] : (int)ei64[E + e];
    float w = ew[e];
    atomicAdd(&g_deg[c], w);
    int ms = g_mapS2[c];
    if (ms >= 0) {
        int r = is32 ? ei32[e] : (int)ei64[e];
        int slot = atomicAdd(&g_l2e_count, 1);
        if (slot < MAX_L2E) {
            g_l2_row[slot]   = r;
            g_l2_cslot[slot] = ms;
            g_l2_w[slot]     = w;
        }
    }
}

// Build S1 = rows(layer-2 edges) ∪ S2, deduped via CAS on g_mapS1.
__global__ void k_build_s1() {
    int t = blockIdx.x * blockDim.x + threadIdx.x;
    int nl2 = min(g_l2e_count, MAX_L2E);
    int ns2 = min(g_s2_count, MAX_S2);
    int node = -1;
    if (t < nl2)             node = g_l2_row[t];
    else if (t < nl2 + ns2)  node = g_s2_node[t - nl2];
    if (node < 0) return;
    int old = atomicCAS(&g_mapS1[node], -1, 0x7FFFFFFF);
    if (old == -1) {
        int slot = atomicAdd(&g_s1_count, 1);
        g_s1_node[slot] = node;   // slot < MAX_S1 guaranteed (nl2+ns2 <= MAX_S1)
        g_mapS1[node]   = slot;
    }
}

// Edge scan 2: accumulate norm * x[row] into agg0 for edges into S1.
__global__ void k_scan2(const long long* __restrict__ ei64,
                        const float* __restrict__ ew,
                        const float* __restrict__ x, int E) {
    int e = blockIdx.x * blockDim.x + threadIdx.x;
    if (e >= E) return;
    int is32 = g_is32;
    const int* ei32 = (const int*)ei64;
    int c = is32 ? ei32[E + e] : (int)ei64[E + e];
    int s = g_mapS1[c];
    if (s < 0) return;
    int r = is32 ? ei32[e] : (int)ei64[e];
    float w = ew[e];
    float norm = w * rsqrtf(g_deg[r] + 1.0f) * rsqrtf(g_deg[c] + 1.0f);
    const float4* xr = (const float4*)(x + (size_t)r * 128);
    float* a = g_agg0 + s * 128;
#pragma unroll
    for (int k = 0; k < 32; k++) {
        float4 v = xr[k];
        atomicAdd(&a[4 * k + 0], norm * v.x);
        atomicAdd(&a[4 * k + 1], norm * v.y);
        atomicAdd(&a[4 * k + 2], norm * v.z);
        atomicAdd(&a[4 * k + 3], norm * v.w);
    }
}

// Layer 1: h1[s] = relu((agg0[s] + x[node]/deg) @ W1 + b1)   [128 -> 256]
__global__ void k_layer1(const float* __restrict__ x,
                         const float* __restrict__ W1,
                         const float* __restrict__ b1) {
    __shared__ float sh[128];
    int ns1 = g_s1_count;
    for (int s = blockIdx.x; s < ns1; s += gridDim.x) {
        int node = g_s1_node[s];
        float inv = 1.0f / (g_deg[node] + 1.0f);   // self-loop norm = dinv^2
        if (threadIdx.x < 128)
            sh[threadIdx.x] = g_agg0[s * 128 + threadIdx.x] +
                              x[(size_t)node * 128 + threadIdx.x] * inv;
        __syncthreads();
        int j = threadIdx.x;
        float acc = b1[j];
#pragma unroll 8
        for (int k = 0; k < 128; k++) acc += sh[k] * W1[k * 256 + j];
        g_h1[s * 256 + j] = fmaxf(acc, 0.0f);
        __syncthreads();
    }
}

// Aggregate layer-2 neighborhoods: agg1[cslot] += norm * h1[rslot] (+ self loop)
__global__ void k_agg1() {
    int nl2 = min(g_l2e_count, MAX_L2E);
    int ns2 = min(g_s2_count, MAX_S2);
    int total = nl2 + ns2;
    int j = threadIdx.x;  // 256
    for (int it = blockIdx.x; it < total; it += gridDim.x) {
        if (it < nl2) {
            int cslot = g_l2_cslot[it];
            int rnode = g_l2_row[it];
            int cnode = g_s2_node[cslot];
            int rslot = g_mapS1[rnode];
            float norm = g_l2_w[it] * rsqrtf(g_deg[rnode] + 1.0f)
                                    * rsqrtf(g_deg[cnode] + 1.0f);
            atomicAdd(&g_agg1[cslot * 256 + j], norm * g_h1[rslot * 256 + j]);
        } else {
            int cslot = it - nl2;
            int cnode = g_s2_node[cslot];
            int cs    = g_mapS1[cnode];
            float inv = 1.0f / (g_deg[cnode] + 1.0f);
            atomicAdd(&g_agg1[cslot * 256 + j], inv * g_h1[cs * 256 + j]);
        }
    }
}

// Layer 2 + masked sum: z += mask_val * relu(agg1 @ W2 + b2)   [256 -> 256]
__global__ void k_layer2(const float* __restrict__ W2,
                         const float* __restrict__ b2) {
    __shared__ float sh[256];
    int ns2 = min(g_s2_count, MAX_S2);
    for (int s = blockIdx.x; s < ns2; s += gridDim.x) {
        sh[threadIdx.x] = g_agg1[s * 256 + threadIdx.x];
        __syncthreads();
        int j = threadIdx.x;
        float acc = b2[j];
#pragma unroll 8
        for (int k = 0; k < 256; k++) acc += sh[k] * W2[k * 256 + j];
        acc = fmaxf(acc, 0.0f);
        atomicAdd(&g_z[j], g_s2_val[s] * acc);
        __syncthreads();
    }
}

// MLP head: feat[480] = [z | wt | mut | mut-wt | pos_emb[pos]] -> 512 -> 128 -> 1
__global__ void k_head(const float* __restrict__ aa_emb,
                       const float* __restrict__ pos_emb,
                       const long long* __restrict__ wt_idx,
                       const long long* __restrict__ mut_idx,
                       const float* __restrict__ Wh1, const float* __restrict__ bh1,
                       const float* __restrict__ Wh2, const float* __restrict__ bh2,
                       const float* __restrict__ Wh3, const float* __restrict__ bh3,
                       float* __restrict__ out, int max_pos) {
    __shared__ float feat[480];
    __shared__ float f1[512];
    __shared__ float f2[128];
    int t = threadIdx.x;  // 512
    int is32 = g_is32;
    int wtI  = is32 ? ((const int*)wt_idx)[0]  : (int)wt_idx[0];
    int mutI = is32 ? ((const int*)mut_idx)[0] : (int)mut_idx[0];

    if (t < 256)       feat[t] = g_z[t];
    else if (t < 320)  feat[t] = aa_emb[wtI  * 64 + (t - 256)];
    else if (t < 384)  feat[t] = aa_emb[mutI * 64 + (t - 320)];
    else if (t < 448)  feat[t] = aa_emb[mutI * 64 + (t - 384)] -
                                 aa_emb[wtI  * 64 + (t - 384)];
    else if (t < 480) {
        unsigned int low = (unsigned int)(g_argmax_key & 0xFFFFFFFFull);
        int pos = (int)(0xFFFFFFFFu - low);
        if (pos < 0) pos = 0;
        if (pos > max_pos - 1) pos = max_pos - 1;
        feat[t] = pos_emb[pos * 32 + (t - 448)];
    }
    __syncthreads();
    {
        float acc = bh1[t];
#pragma unroll 8
        for (int k = 0; k < 480; k++) acc += feat[k] * Wh1[k * 512 + t];
        f1[t] = fmaxf(acc, 0.0f);
    }
    __syncthreads();
    if (t < 128) {
        float acc = bh2[t];
#pragma unroll 8
        for (int k = 0; k < 512; k++) acc += f1[k] * Wh2[k * 128 + t];
        f2[t] = fmaxf(acc, 0.0f) * Wh3[t];
    }
    __syncthreads();
    if (t < 64) f2[t] += f2[t + 64];
    __syncthreads();
    if (t < 32) {
        float v = f2[t] + f2[t + 32];
        for (int o = 16; o > 0; o >>= 1) v += __shfl_down_sync(0xFFFFFFFFu, v, o);
        if (t == 0) out[0] = v + bh3[0];
    }
}

// ---------------------------------------------------------------------------
extern "C" void kernel_launch(void* const* d_in, const int* in_sizes, int n_in,
                              void* d_out, int out_size) {
    const float*     x       = (const float*)d_in[0];
    const long long* ei      = (const long long*)d_in[1];
    const float*     ew      = (const float*)d_in[2];
    const float*     mask    = (const float*)d_in[3];
    const long long* wt_idx  = (const long long*)d_in[4];
    const long long* mut_idx = (const long long*)d_in[5];
    const float*     W1      = (const float*)d_in[6];
    const float*     b1      = (const float*)d_in[7];
    const float*     W2      = (const float*)d_in[8];
    const float*     b2      = (const float*)d_in[9];
    const float*     aa_emb  = (const float*)d_in[10];
    const float*     pos_emb = (const float*)d_in[11];
    const float*     Wh1     = (const float*)d_in[12];
    const float*     bh1     = (const float*)d_in[13];
    const float*     Wh2     = (const float*)d_in[14];
    const float*     bh2     = (const float*)d_in[15];
    const float*     Wh3     = (const float*)d_in[16];
    const float*     bh3     = (const float*)d_in[17];
    float*           out     = (float*)d_out;

    int n       = in_sizes[3];            // mut_mask length = N
    int E       = in_sizes[2];            // edge_weight length = E
    int max_pos = in_sizes[11] / 32;      // pos_emb rows

    int initM = MAX_S1 * 128;             // largest array the init kernel touches
    if (n > initM) initM = n;

    k_init   <<<(initM + 255) / 256, 256>>>(n);
    k_detect <<<16, 256>>>(ei, E, n);
    k_mask   <<<(n + 255) / 256, 256>>>(mask, n);
    k_scan1  <<<(E + 255) / 256, 256>>>(ei, ew, E);
    k_build_s1 <<<(MAX_L2E + MAX_S2 + 255) / 256, 256>>>();
    k_scan2  <<<(E + 255) / 256, 256>>>(ei, ew, x, E);
    k_layer1 <<<128, 256>>>(x, W1, b1);
    k_agg1   <<<64, 256>>>();
    k_layer2 <<<32, 256>>>(W2, b2);
    k_head   <<<1, 512>>>(aa_emb, pos_emb, wt_idx, mut_idx,
                          Wh1, bh1, Wh2, bh2, Wh3, bh3, out, max_pos);
}